// round 14
// baseline (speedup 1.0000x reference)
#include <cuda_runtime.h>
#include <cuda_fp16.h>
#include <stdint.h>

#define Bb 8
#define Cc 2048
#define Nn 8000
#define Hh 256
#define Oo 1000
#define Op 1024
#define NTILE 63
#define STAGE_A 20480            // 256 rows x 80B (32 f16 + 16B pad)
#define STAGE_B 8704             // 32 k-rows x 272B (128 f16 + 16B pad)
#define STAGE_BYTES (STAGE_A + STAGE_B)
#define NSTAGE 3
#define RING_OFF (NSTAGE * STAGE_BYTES)           // 87552
#define RING_SLOT 16384                           // 32 rows x 128 cols fp32 (thread-private 32B)
#define SMEM_H (RING_OFF + 4 * RING_SLOT)         // 153088 (h0 and h1 aliased here)
#define DYN_SMEM (SMEM_H + 256 * 272)             // 222720

__device__ __align__(16) __half g_W0h[Hh * Cc];
__device__ __align__(16) __half g_W1h[Hh * Hh];
__device__ __align__(16) __half g_W2h[Op * Hh];
__device__ __align__(16) __half g_y [(size_t)Bb * Oo * Nn];   // fp16 y
__device__ float g_mask[Bb * Nn];
__device__ float g_coef[Bb * 128];

__device__ __forceinline__ uint32_t smem_u32(const void* p) {
    uint32_t a;
    asm("{ .reg .u64 t; cvta.to.shared.u64 t, %1; cvt.u32.u64 %0, t; }" : "=r"(a) : "l"(p));
    return a;
}
__device__ __forceinline__ void cp16(uint32_t dst, const void* src, int bytes) {
    asm volatile("cp.async.cg.shared.global [%0], [%1], 16, %2;\n"
                 :: "r"(dst), "l"(src), "r"(bytes) : "memory");
}
#define CP_COMMIT() asm volatile("cp.async.commit_group;\n" ::: "memory")
#define CP_WAIT0()  asm volatile("cp.async.wait_group 0;\n" ::: "memory")
#define CP_WAIT1()  asm volatile("cp.async.wait_group 1;\n" ::: "memory")

__device__ __forceinline__ void ldm_x4(uint32_t* r, const void* p) {
    uint32_t a = (uint32_t)__cvta_generic_to_shared(p);
    asm volatile("ldmatrix.sync.aligned.m8n8.x4.shared.b16 {%0,%1,%2,%3}, [%4];\n"
                 : "=r"(r[0]), "=r"(r[1]), "=r"(r[2]), "=r"(r[3]) : "r"(a));
}
__device__ __forceinline__ void ldm_x4t(uint32_t* r, const void* p) {
    uint32_t a = (uint32_t)__cvta_generic_to_shared(p);
    asm volatile("ldmatrix.sync.aligned.m8n8.x4.trans.shared.b16 {%0,%1,%2,%3}, [%4];\n"
                 : "=r"(r[0]), "=r"(r[1]), "=r"(r[2]), "=r"(r[3]) : "r"(a));
}
__device__ __forceinline__ void mma16816(float* d, const uint32_t* a, uint32_t b0, uint32_t b1) {
    asm volatile("mma.sync.aligned.m16n8k16.row.col.f32.f16.f16.f32 "
                 "{%0,%1,%2,%3}, {%4,%5,%6,%7}, {%8,%9}, {%0,%1,%2,%3};\n"
                 : "+f"(d[0]), "+f"(d[1]), "+f"(d[2]), "+f"(d[3])
                 : "r"(a[0]), "r"(a[1]), "r"(a[2]), "r"(a[3]), "r"(b0), "r"(b1));
}
__device__ __forceinline__ uint32_t h2u(__half2 h) { return *reinterpret_cast<uint32_t*>(&h); }

__device__ __forceinline__ void compute_iter(char* aB, char* bB, float d[4][4][4]) {
#pragma unroll
    for (int s = 0; s < 2; ++s) {
        uint32_t a[4][4];
#pragma unroll
        for (int mf = 0; mf < 4; ++mf) ldm_x4(a[mf], aB + mf * 16 * 80 + s * 32);
#pragma unroll
        for (int nf2 = 0; nf2 < 2; ++nf2) {
            uint32_t bq[4];
            ldm_x4t(bq, bB + s * 16 * 272 + nf2 * 32);
#pragma unroll
            for (int mf = 0; mf < 4; ++mf) {
                mma16816(d[mf][nf2 * 2],     a[mf], bq[0], bq[1]);
                mma16816(d[mf][nf2 * 2 + 1], a[mf], bq[2], bq[3]);
            }
        }
    }
}

// ---------------------------------------------------------------------------
// Fused 3-layer MLP per (b, n-tile of 128). h0/h1 share ONE smem tile
// (phase 2 fully consumes h0 before writing h1). Phase-1 x feed goes through
// a 4-slot cp.async fp32 ring (2-iteration guaranteed slack, no RF pipeline).
// ---------------------------------------------------------------------------
__global__ __launch_bounds__(512, 1) void fused_mlp(const float* __restrict__ x,
                                                    const float* __restrict__ b0,
                                                    const float* __restrict__ b1,
                                                    const float* __restrict__ b2) {
    extern __shared__ __align__(16) char dyn[];
    const uint32_t sm0 = smem_u32(dyn);
    __shared__ int s_any[128];

    const int tid = threadIdx.x, lane = tid & 31, warp = tid >> 5;
    const int wm = warp >> 2, wn = warp & 3;
    const int b = blockIdx.z, n0 = blockIdx.x * 128;

    const float* xb = x + (size_t)b * Cc * Nn;

    const int ar0 = tid >> 2, aseg = tid & 3;
    const int br = tid >> 4, bseg = tid & 15;
    const int bn = n0 + bseg * 8;
    const int bnc = (bn < Nn) ? bn : 0;
    const int xbytes = (bn < Nn) ? 16 : 0;

    char* const aLane = dyn + (wm * 64 + (lane & 15)) * 80 + ((lane >> 4) << 4);
    const int   bLane = (((lane >> 3) & 1) * 8 + (lane & 7)) * 272
                      + (wn * 32 + ((lane >> 4) << 3)) * 2;

    auto load_stageA = [&](int st, int kk, const __half* W, int Kd) {
        const uint32_t sa = sm0 + st * STAGE_BYTES;
        const int k0 = kk * 32;
        cp16(sa + ar0 * 80 + aseg * 16, W + (size_t)ar0 * Kd + k0 + aseg * 8, 16);
        cp16(sa + (ar0 + 128) * 80 + aseg * 16,
             W + (size_t)(ar0 + 128) * Kd + k0 + aseg * 8, 16);
    };

    // x chunk -> ring slot (thread-private 32B line; coalesced 16B cp.async)
    auto xload = [&](int chunk) {
        uint32_t dst = sm0 + RING_OFF + (chunk & 3) * RING_SLOT + tid * 32;
        const float* p = xb + (size_t)(chunk * 32 + br) * Nn + bnc;
        cp16(dst, p, xbytes);
        cp16(dst + 16, p + 4, xbytes);
    };

    __half2 hm[4];
#pragma unroll
    for (int j = 0; j < 4; ++j) hm[j] = __floats2half2_rn(0.f, 0.f);
    if (tid < 128) s_any[tid] = 0;

    // ring chunk -> fp16 B-stage (chunk%3), with running hmax
    auto xconv = [&](int chunk) {
        char* rp = dyn + RING_OFF + (chunk & 3) * RING_SLOT + tid * 32;
        float4 a = *(const float4*)rp;
        float4 c = *(const float4*)(rp + 16);
        __half2 h0 = __floats2half2_rn(a.x, a.y), h1 = __floats2half2_rn(a.z, a.w);
        __half2 h2 = __floats2half2_rn(c.x, c.y), h3 = __floats2half2_rn(c.z, c.w);
        hm[0] = __hmax2(hm[0], h0); hm[1] = __hmax2(hm[1], h1);
        hm[2] = __hmax2(hm[2], h2); hm[3] = __hmax2(hm[3], h3);
        uint32_t dst = sm0 + (chunk % 3) * STAGE_BYTES + STAGE_A + br * 272 + bseg * 16;
        asm volatile("st.shared.v4.b32 [%0], {%1,%2,%3,%4};\n"
                     :: "r"(dst), "r"(h2u(h0)), "r"(h2u(h1)), "r"(h2u(h2)), "r"(h2u(h3))
                     : "memory");
    };

    float d[4][4][4];
    auto zero_acc = [&]() {
#pragma unroll
        for (int i = 0; i < 4; ++i)
#pragma unroll
            for (int j = 0; j < 4; ++j) { d[i][j][0]=0.f; d[i][j][1]=0.f; d[i][j][2]=0.f; d[i][j][3]=0.f; }
    };
    auto epi_smem = [&](char* hs, const float* __restrict__ bias) {
#pragma unroll
        for (int mf = 0; mf < 4; ++mf) {
            int o = wm * 64 + mf * 16 + (lane >> 2);
            float bs0 = bias[o], bs1 = bias[o + 8];
#pragma unroll
            for (int nf = 0; nf < 4; ++nf) {
                int nl = wn * 32 + nf * 8 + (lane & 3) * 2;
                float v0 = fminf(fmaxf(d[mf][nf][0] + bs0, 0.f), 1e4f);
                float v1 = fminf(fmaxf(d[mf][nf][1] + bs0, 0.f), 1e4f);
                float v2 = fminf(fmaxf(d[mf][nf][2] + bs1, 0.f), 1e4f);
                float v3 = fminf(fmaxf(d[mf][nf][3] + bs1, 0.f), 1e4f);
                *(uint32_t*)(hs + o * 272 + nl * 2)       = h2u(__floats2half2_rn(v0, v1));
                *(uint32_t*)(hs + (o + 8) * 272 + nl * 2) = h2u(__floats2half2_rn(v2, v3));
            }
        }
    };

    // ================== Phase 1: h0 = act(W0 @ x), K = 2048 ==================
    zero_acc();
    {
        constexpr int NIT = Cc / 32;   // 64
        // prologue groups: A={W0,x0}, B={W1,x1}, C={x2}
        load_stageA(0, 0, g_W0h, Cc); xload(0); CP_COMMIT();
        load_stageA(1, 1, g_W0h, Cc); xload(1); CP_COMMIT();
        xload(2); CP_COMMIT();
        CP_WAIT1();          // A, B complete (W0, W1, x0, x1)
        __syncthreads();
        xconv(0);            // B-stage 0
        __syncthreads();

#pragma unroll 1
        for (int j = 0; j < NIT; ++j) {
            if (j + 2 < NIT) load_stageA((j + 2) % 3, j + 2, g_W0h, Cc);
            if (j + 3 < NIT) xload(j + 3);
            CP_COMMIT();     // uniform group counting (empty groups at tail)
            if (j + 1 < NIT) xconv(j + 1);
            compute_iter(aLane + (j % 3) * STAGE_BYTES,
                         dyn + (j % 3) * STAGE_BYTES + STAGE_A + bLane, d);
            CP_WAIT1();      // completes through G_{j-1}: W j+1, x j+2 ready
            __syncthreads();
        }
    }
    epi_smem(dyn + SMEM_H, b0);   // h0 -> shared tile
#pragma unroll
    for (int j = 0; j < 4; ++j) {
        if (__low2float(hm[j])  > 0.f) atomicOr(&s_any[bseg * 8 + 2 * j],     1);
        if (__high2float(hm[j]) > 0.f) atomicOr(&s_any[bseg * 8 + 2 * j + 1], 1);
    }
    __syncthreads();
    if (tid < 128 && n0 + tid < Nn)
        g_mask[b * Nn + n0 + tid] = s_any[tid] ? 1.f : 0.f;

    // ================== Phase 2: h1 = act(W1 @ h0), K = 256 ==================
    zero_acc();
    {
        constexpr int NIT = Hh / 32;   // 8
        load_stageA(0, 0, g_W1h, Hh); CP_COMMIT();
        load_stageA(1, 1, g_W1h, Hh); CP_COMMIT();
        CP_WAIT1();
        __syncthreads();
#pragma unroll 1
        for (int k = 0; k < NIT; ++k) {
            const int st = k % NSTAGE;
            if (k + 2 < NIT) { load_stageA((k + 2) % NSTAGE, k + 2, g_W1h, Hh); CP_COMMIT(); }
            compute_iter(aLane + st * STAGE_BYTES,
                         dyn + SMEM_H + k * (32 * 272) + bLane, d);
            if (k + 2 < NIT)      { CP_WAIT1(); }
            else if (k + 1 < NIT) { CP_WAIT0(); }
            __syncthreads();
        }
    }
    // h0 fully consumed (loop ends with barrier) -> overwrite tile with h1
    epi_smem(dyn + SMEM_H, b1);
    __syncthreads();

    // ============ Phase 3: y = (W2 @ h1 + b2) * mask -> fp16 ============
    __half* yp = g_y + (size_t)b * Oo * Nn;
#pragma unroll 1
    for (int oc = 0; oc < 4; ++oc) {
        const __half* W2c = g_W2h + (size_t)oc * 256 * Hh;
        zero_acc();
        constexpr int NIT = Hh / 32;
        load_stageA(0, 0, W2c, Hh); CP_COMMIT();
        load_stageA(1, 1, W2c, Hh); CP_COMMIT();
        CP_WAIT1();
        __syncthreads();
#pragma unroll 1
        for (int k = 0; k < NIT; ++k) {
            const int st = k % NSTAGE;
            if (k + 2 < NIT) { load_stageA((k + 2) % NSTAGE, k + 2, W2c, Hh); CP_COMMIT(); }
            compute_iter(aLane + st * STAGE_BYTES,
                         dyn + SMEM_H + k * (32 * 272) + bLane, d);
            if (k + 2 < NIT)      { CP_WAIT1(); }
            else if (k + 1 < NIT) { CP_WAIT0(); }
            __syncthreads();
        }
#pragma unroll
        for (int mf = 0; mf < 4; ++mf) {
            int o = oc * 256 + wm * 64 + mf * 16 + (lane >> 2);
#pragma unroll
            for (int nf = 0; nf < 4; ++nf) {
                int nl = wn * 32 + nf * 8 + (lane & 3) * 2;
                int n = n0 + nl;
                if (n < Nn) {
                    float mk0 = s_any[nl] ? 1.f : 0.f;
                    float mk1 = s_any[nl + 1] ? 1.f : 0.f;
                    if (o < Oo) {
                        float bs = b2[o];
                        *(uint32_t*)(yp + (size_t)o * Nn + n) =
                            h2u(__floats2half2_rn((d[mf][nf][0] + bs) * mk0,
                                                  (d[mf][nf][1] + bs) * mk1));
                    }
                    if (o + 8 < Oo) {
                        float bs = b2[o + 8];
                        *(uint32_t*)(yp + (size_t)(o + 8) * Nn + n) =
                            h2u(__floats2half2_rn((d[mf][nf][2] + bs) * mk0,
                                                  (d[mf][nf][3] + bs) * mk1));
                    }
                }
            }
        }
        __syncthreads();
    }
}

template <int WSEL>
__global__ void wconv_kernel(const float* __restrict__ W, int rows, int cols, int orows) {
    __half* outp = (WSEL == 0) ? g_W0h : (WSEL == 1) ? g_W1h : g_W2h;
    int i = blockIdx.x * 256 + threadIdx.x;
    if (i >= orows * cols) return;
    int r = i / cols, c = i - r * cols;
    outp[(size_t)r * cols + c] = __float2half_rn((r < rows) ? W[(size_t)r * cols + c] : 0.f);
}

__global__ void coef_kernel() {
    int b = threadIdx.x;
    if (b >= Bb) return;
    float s = 0.f, d10 = 0.f, d25 = 0.f, d50 = 0.f;
    for (int j = 0; j < 100; ++j) {
        s += g_mask[b * Nn + j];
        if (j == 9)  d10 = s;
        if (j == 24) d25 = s;
        if (j == 49) d50 = s;
    }
    float d100 = s;
    for (int j = 0; j < 100; ++j) {
        float w = 0.25f / d100;
        if (j < 50) w += 0.25f / d50;
        if (j < 25) w += 0.25f / d25;
        if (j < 10) w += 0.25f / d10;
        g_coef[b * 128 + j] = g_mask[b * Nn + j] * w;
    }
}

// ---------------------------------------------------------------------------
// Top-100 over fp16 y: 12-bit first radix level (4096 packed u16 counters),
// parallel suffix-scan selection, 4-bit level 2. (round-12/13 proven version)
// ---------------------------------------------------------------------------
__global__ __launch_bounds__(256) void topk_kernel(float* __restrict__ out) {
    const int row = blockIdx.x, b = row / Oo, tid = threadIdx.x;
    __shared__ uint16_t su[Nn];          // 16000 B
    __shared__ uint32_t hist[2048];      // 4096 packed 16-bit counters (8KB)
    __shared__ uint32_t csum[256];
    __shared__ uint32_t s_sel[2];
    __shared__ uint32_t s_cnt;
    __shared__ uint32_t buf[128];
    __shared__ uint32_t srt[128];
    __shared__ float partial[256];

    for (int i = tid; i < 2048; i += 256) hist[i] = 0;

    const uint32_t* yp = (const uint32_t*)(g_y + (size_t)row * Nn);
    for (int i = tid; i < Nn / 2; i += 256) {
        uint32_t two = yp[i];
        uint32_t lo = two & 0xFFFFu, hi = two >> 16;
        su[2 * i]     = (uint16_t)((lo & 0x8000u) ? (~lo & 0xFFFFu) : (lo | 0x8000u));
        su[2 * i + 1] = (uint16_t)((hi & 0x8000u) ? (~hi & 0xFFFFu) : (hi | 0x8000u));
    }
    __syncthreads();

    for (int i = tid; i < Nn; i += 256) {
        uint32_t bin = (uint32_t)su[i] >> 4;
        atomicAdd(&hist[bin >> 1], 1u << ((bin & 1) * 16));
    }
    __syncthreads();

    {
        uint32_t cs = 0;
#pragma unroll
        for (int w = 0; w < 8; ++w) {
            uint32_t v = hist[tid * 8 + w];
            cs += (v & 0xFFFFu) + (v >> 16);
        }
        csum[tid] = cs;
    }
    __syncthreads();
#pragma unroll
    for (int off = 1; off < 256; off <<= 1) {
        uint32_t v = (tid + off < 256) ? csum[tid + off] : 0;
        __syncthreads();
        csum[tid] += v;
        __syncthreads();
    }
    int K = 100;
    {
        uint32_t sfx = csum[tid];
        uint32_t nxt = (tid < 255) ? csum[tid + 1] : 0;
        if (sfx >= (uint32_t)K && nxt < (uint32_t)K) {
            uint32_t above = nxt;
            int binSel = tid * 16;
            for (int bl = 15; bl >= 0; --bl) {
                int gb = tid * 16 + bl;
                uint32_t c = (hist[gb >> 1] >> ((gb & 1) * 16)) & 0xFFFFu;
                if (above + c >= (uint32_t)K) { binSel = gb; break; }
                above += c;
            }
            s_sel[0] = (uint32_t)binSel;
            s_sel[1] = (uint32_t)K - above;
        }
    }
    __syncthreads();
    const uint32_t bin12 = s_sel[0];
    K = (int)s_sel[1];
    __syncthreads();

    if (tid < 16) csum[tid] = 0;
    __syncthreads();
    for (int i = tid; i < Nn; i += 256) {
        uint32_t v = su[i];
        if ((v >> 4) == bin12) atomicAdd(&csum[v & 15u], 1u);
    }
    __syncthreads();
    if (tid == 0) {
        int cum = 0, bl = 15;
        for (; bl > 0; --bl) {
            int c = (int)csum[bl];
            if (cum + c >= K) break;
            cum += c;
        }
        s_sel[0] = (bin12 << 4) | (uint32_t)bl;
    }
    __syncthreads();
    const uint32_t thr = s_sel[0];

    if (tid == 0) s_cnt = 0;
    __syncthreads();
    for (int i = tid; i < Nn; i += 256) {
        uint32_t v = su[i];
        if (v > thr) {
            uint32_t idx = atomicAdd(&s_cnt, 1u);
            if (idx < 128u) buf[idx] = v;
        }
    }
    __syncthreads();
    int g = (int)min(s_cnt, 100u);
    for (int j = g + tid; j < 100; j += 256) buf[j] = thr;
    __syncthreads();

    if (tid < 100) {
        uint32_t v = buf[tid];
        int rank = 0;
#pragma unroll 4
        for (int j = 0; j < 100; ++j) {
            uint32_t w = buf[j];
            rank += (w > v) || (w == v && j < tid);
        }
        srt[rank] = v;
    }
    __syncthreads();
    float t = 0.f;
    if (tid < 100) {
        uint32_t u = srt[tid];
        uint16_t bits = (u & 0x8000u) ? (uint16_t)(u & 0x7FFFu) : (uint16_t)(~u & 0xFFFFu);
        t = __half2float(__ushort_as_half(bits)) * g_coef[b * 128 + tid];
    }
    partial[tid] = t;
    __syncthreads();
    for (int s = 128; s > 0; s >>= 1) {
        if (tid < s) partial[tid] += partial[tid + s];
        __syncthreads();
    }
    if (tid == 0) out[row] = partial[0];
}

extern "C" void kernel_launch(void* const* d_in, const int* in_sizes, int n_in,
                              void* d_out, int out_size) {
    const float* x  = (const float*)d_in[0];
    const float* W0 = (const float*)d_in[1];
    const float* b0 = (const float*)d_in[2];
    const float* W1 = (const float*)d_in[3];
    const float* b1 = (const float*)d_in[4];
    const float* W2 = (const float*)d_in[5];
    const float* b2 = (const float*)d_in[6];
    float* out = (float*)d_out;
    (void)in_sizes; (void)n_in; (void)out_size;

    cudaFuncSetAttribute(fused_mlp, cudaFuncAttributeMaxDynamicSharedMemorySize, DYN_SMEM);

    wconv_kernel<0><<<(Hh * Cc + 255) / 256, 256>>>(W0, Hh, Cc, Hh);
    wconv_kernel<1><<<(Hh * Hh + 255) / 256, 256>>>(W1, Hh, Hh, Hh);
    wconv_kernel<2><<<(Op * Hh + 255) / 256, 256>>>(W2, Oo, Hh, Op);

    fused_mlp<<<dim3(NTILE, 1, Bb), 512, DYN_SMEM>>>(x, b0, b1, b2);

    coef_kernel<<<1, 32>>>();
    topk_kernel<<<Bb * Oo, 256>>>(out);
}

// round 15
// speedup vs baseline: 1.0251x; 1.0251x over previous
#include <cuda_runtime.h>
#include <cuda_fp16.h>
#include <stdint.h>

#define Bb 8
#define Cc 2048
#define Nn 8000
#define Hh 256
#define Oo 1000
#define Op 1024
#define NTILE 63
#define STAGE_A 20480            // 256 rows x 80B (32 f16 + 16B pad)
#define STAGE_B 8704             // 32 k-rows x 272B (128 f16 + 16B pad)
#define STAGE_BYTES (STAGE_A + STAGE_B)
#define NSTAGE 3
#define SMEM_H0 (NSTAGE * STAGE_BYTES)            // 87552
#define SMEM_H1 (SMEM_H0 + 256 * 272)             // 157184
#define DYN_SMEM (SMEM_H1 + 256 * 272)            // 226816

__device__ __align__(16) __half g_W0h[Hh * Cc];
__device__ __align__(16) __half g_W1h[Hh * Hh];
__device__ __align__(16) __half g_W2h[Op * Hh];
__device__ __align__(16) __half g_y [(size_t)Bb * Oo * Nn];   // fp16 y
__device__ float g_mask[Bb * Nn];
__device__ float g_coef[Bb * 128];

__device__ __forceinline__ uint32_t smem_u32(const void* p) {
    uint32_t a;
    asm("{ .reg .u64 t; cvta.to.shared.u64 t, %1; cvt.u32.u64 %0, t; }" : "=r"(a) : "l"(p));
    return a;
}
__device__ __forceinline__ void cp16(uint32_t dst, const void* src, int bytes) {
    asm volatile("cp.async.cg.shared.global [%0], [%1], 16, %2;\n"
                 :: "r"(dst), "l"(src), "r"(bytes) : "memory");
}
#define CP_COMMIT() asm volatile("cp.async.commit_group;\n" ::: "memory")
#define CP_WAIT0()  asm volatile("cp.async.wait_group 0;\n" ::: "memory")
#define CP_WAIT1()  asm volatile("cp.async.wait_group 1;\n" ::: "memory")

__device__ __forceinline__ void ldm_x4(uint32_t* r, const void* p) {
    uint32_t a = (uint32_t)__cvta_generic_to_shared(p);
    asm volatile("ldmatrix.sync.aligned.m8n8.x4.shared.b16 {%0,%1,%2,%3}, [%4];\n"
                 : "=r"(r[0]), "=r"(r[1]), "=r"(r[2]), "=r"(r[3]) : "r"(a));
}
__device__ __forceinline__ void ldm_x4t(uint32_t* r, const void* p) {
    uint32_t a = (uint32_t)__cvta_generic_to_shared(p);
    asm volatile("ldmatrix.sync.aligned.m8n8.x4.trans.shared.b16 {%0,%1,%2,%3}, [%4];\n"
                 : "=r"(r[0]), "=r"(r[1]), "=r"(r[2]), "=r"(r[3]) : "r"(a));
}
__device__ __forceinline__ void mma16816(float* d, const uint32_t* a, uint32_t b0, uint32_t b1) {
    asm volatile("mma.sync.aligned.m16n8k16.row.col.f32.f16.f16.f32 "
                 "{%0,%1,%2,%3}, {%4,%5,%6,%7}, {%8,%9}, {%0,%1,%2,%3};\n"
                 : "+f"(d[0]), "+f"(d[1]), "+f"(d[2]), "+f"(d[3])
                 : "r"(a[0]), "r"(a[1]), "r"(a[2]), "r"(a[3]), "r"(b0), "r"(b1));
}
__device__ __forceinline__ uint32_t h2u(__half2 h) { return *reinterpret_cast<uint32_t*>(&h); }

__device__ __forceinline__ void compute_iter(char* aB, char* bB, float d[4][4][4]) {
#pragma unroll
    for (int s = 0; s < 2; ++s) {
        uint32_t a[4][4];
#pragma unroll
        for (int mf = 0; mf < 4; ++mf) ldm_x4(a[mf], aB + mf * 16 * 80 + s * 32);
#pragma unroll
        for (int nf2 = 0; nf2 < 2; ++nf2) {
            uint32_t bq[4];
            ldm_x4t(bq, bB + s * 16 * 272 + nf2 * 32);
#pragma unroll
            for (int mf = 0; mf < 4; ++mf) {
                mma16816(d[mf][nf2 * 2],     a[mf], bq[0], bq[1]);
                mma16816(d[mf][nf2 * 2 + 1], a[mf], bq[2], bq[3]);
            }
        }
    }
}

// ---------------------------------------------------------------------------
// Fused 3-layer MLP per (b, n-tile of 128). h0/h1 stay in smem.
// (round-13 proven version — 474 us)
// ---------------------------------------------------------------------------
__global__ __launch_bounds__(512, 1) void fused_mlp(const float* __restrict__ x,
                                                    const float* __restrict__ b0,
                                                    const float* __restrict__ b1,
                                                    const float* __restrict__ b2) {
    extern __shared__ __align__(16) char dyn[];
    const uint32_t sm0 = smem_u32(dyn);
    __shared__ int s_any[128];

    const int tid = threadIdx.x, lane = tid & 31, warp = tid >> 5;
    const int wm = warp >> 2, wn = warp & 3;
    const int b = blockIdx.z, n0 = blockIdx.x * 128;

    const float* xb = x + (size_t)b * Cc * Nn;

    const int ar0 = tid >> 2, aseg = tid & 3;
    const int br = tid >> 4, bseg = tid & 15;
    const int bn = n0 + bseg * 8;

    char* const aLane = dyn + (wm * 64 + (lane & 15)) * 80 + ((lane >> 4) << 4);
    const int   bLane = (((lane >> 3) & 1) * 8 + (lane & 7)) * 272
                      + (wn * 32 + ((lane >> 4) << 3)) * 2;

    auto load_stageA = [&](int st, int kk, const __half* W, int Kd) {
        const uint32_t sa = sm0 + st * STAGE_BYTES;
        const int k0 = kk * 32;
        cp16(sa + ar0 * 80 + aseg * 16, W + (size_t)ar0 * Kd + k0 + aseg * 8, 16);
        cp16(sa + (ar0 + 128) * 80 + aseg * 16,
             W + (size_t)(ar0 + 128) * Kd + k0 + aseg * 8, 16);
    };

    float4 rb0, rb1;
    __half2 hm[4];
#pragma unroll
    for (int j = 0; j < 4; ++j) hm[j] = __floats2half2_rn(0.f, 0.f);
    if (tid < 128) s_any[tid] = 0;

    auto ldgB = [&](int kk, float4& a, float4& c) {
        if (bn < Nn) {
            const float* p = xb + (size_t)(kk * 32 + br) * Nn + bn;
            a = *(const float4*)p; c = *(const float4*)(p + 4);
        } else { a = make_float4(0.f, 0.f, 0.f, 0.f); c = a; }
    };
    auto stsB = [&](int st, const float4& a, const float4& c) {
        __half2 h0 = __floats2half2_rn(a.x, a.y), h1 = __floats2half2_rn(a.z, a.w);
        __half2 h2 = __floats2half2_rn(c.x, c.y), h3 = __floats2half2_rn(c.z, c.w);
        hm[0] = __hmax2(hm[0], h0); hm[1] = __hmax2(hm[1], h1);
        hm[2] = __hmax2(hm[2], h2); hm[3] = __hmax2(hm[3], h3);
        uint32_t dst = sm0 + st * STAGE_BYTES + STAGE_A + br * 272 + bseg * 16;
        asm volatile("st.shared.v4.b32 [%0], {%1,%2,%3,%4};\n"
                     :: "r"(dst), "r"(h2u(h0)), "r"(h2u(h1)), "r"(h2u(h2)), "r"(h2u(h3))
                     : "memory");
    };

    float d[4][4][4];
    auto zero_acc = [&]() {
#pragma unroll
        for (int i = 0; i < 4; ++i)
#pragma unroll
            for (int j = 0; j < 4; ++j) { d[i][j][0]=0.f; d[i][j][1]=0.f; d[i][j][2]=0.f; d[i][j][3]=0.f; }
    };
    auto epi_smem = [&](char* hs, const float* __restrict__ bias) {
#pragma unroll
        for (int mf = 0; mf < 4; ++mf) {
            int o = wm * 64 + mf * 16 + (lane >> 2);
            float bs0 = bias[o], bs1 = bias[o + 8];
#pragma unroll
            for (int nf = 0; nf < 4; ++nf) {
                int nl = wn * 32 + nf * 8 + (lane & 3) * 2;
                float v0 = fminf(fmaxf(d[mf][nf][0] + bs0, 0.f), 1e4f);
                float v1 = fminf(fmaxf(d[mf][nf][1] + bs0, 0.f), 1e4f);
                float v2 = fminf(fmaxf(d[mf][nf][2] + bs1, 0.f), 1e4f);
                float v3 = fminf(fmaxf(d[mf][nf][3] + bs1, 0.f), 1e4f);
                *(uint32_t*)(hs + o * 272 + nl * 2)       = h2u(__floats2half2_rn(v0, v1));
                *(uint32_t*)(hs + (o + 8) * 272 + nl * 2) = h2u(__floats2half2_rn(v2, v3));
            }
        }
    };

    // Phase 1: h0 = act(W0 @ x)
    zero_acc();
    {
        constexpr int NIT = Cc / 32;
        load_stageA(0, 0, g_W0h, Cc);
        { float4 a, c; ldgB(0, a, c); stsB(0, a, c); }
        CP_COMMIT();
        load_stageA(1, 1, g_W0h, Cc);
        ldgB(1, rb0, rb1);
        CP_COMMIT();
        CP_WAIT1();
        __syncthreads();
#pragma unroll 1
        for (int k = 0; k < NIT; ++k) {
            const int st = k % NSTAGE;
            if (k + 2 < NIT) { load_stageA((k + 2) % NSTAGE, k + 2, g_W0h, Cc); }
            if (k + 1 < NIT) stsB((k + 1) % NSTAGE, rb0, rb1);
            if (k + 2 < NIT) { ldgB(k + 2, rb0, rb1); CP_COMMIT(); }
            compute_iter(aLane + st * STAGE_BYTES,
                         dyn + st * STAGE_BYTES + STAGE_A + bLane, d);
            if (k + 2 < NIT)      { CP_WAIT1(); }
            else if (k + 1 < NIT) { CP_WAIT0(); }
            __syncthreads();
        }
    }
    epi_smem(dyn + SMEM_H0, b0);
#pragma unroll
    for (int j = 0; j < 4; ++j) {
        if (__low2float(hm[j])  > 0.f) atomicOr(&s_any[bseg * 8 + 2 * j],     1);
        if (__high2float(hm[j]) > 0.f) atomicOr(&s_any[bseg * 8 + 2 * j + 1], 1);
    }
    __syncthreads();
    if (tid < 128 && n0 + tid < Nn)
        g_mask[b * Nn + n0 + tid] = s_any[tid] ? 1.f : 0.f;

    // Phase 2: h1 = act(W1 @ h0)
    zero_acc();
    {
        constexpr int NIT = Hh / 32;
        load_stageA(0, 0, g_W1h, Hh); CP_COMMIT();
        load_stageA(1, 1, g_W1h, Hh); CP_COMMIT();
        CP_WAIT1();
        __syncthreads();
#pragma unroll 1
        for (int k = 0; k < NIT; ++k) {
            const int st = k % NSTAGE;
            if (k + 2 < NIT) { load_stageA((k + 2) % NSTAGE, k + 2, g_W1h, Hh); CP_COMMIT(); }
            compute_iter(aLane + st * STAGE_BYTES,
                         dyn + SMEM_H0 + k * (32 * 272) + bLane, d);
            if (k + 2 < NIT)      { CP_WAIT1(); }
            else if (k + 1 < NIT) { CP_WAIT0(); }
            __syncthreads();
        }
    }
    epi_smem(dyn + SMEM_H1, b1);
    __syncthreads();

    // Phase 3: y = (W2 @ h1 + b2) * mask  -> fp16
    __half* yp = g_y + (size_t)b * Oo * Nn;
#pragma unroll 1
    for (int oc = 0; oc < 4; ++oc) {
        const __half* W2c = g_W2h + (size_t)oc * 256 * Hh;
        zero_acc();
        constexpr int NIT = Hh / 32;
        load_stageA(0, 0, W2c, Hh); CP_COMMIT();
        load_stageA(1, 1, W2c, Hh); CP_COMMIT();
        CP_WAIT1();
        __syncthreads();
#pragma unroll 1
        for (int k = 0; k < NIT; ++k) {
            const int st = k % NSTAGE;
            if (k + 2 < NIT) { load_stageA((k + 2) % NSTAGE, k + 2, W2c, Hh); CP_COMMIT(); }
            compute_iter(aLane + st * STAGE_BYTES,
                         dyn + SMEM_H1 + k * (32 * 272) + bLane, d);
            if (k + 2 < NIT)      { CP_WAIT1(); }
            else if (k + 1 < NIT) { CP_WAIT0(); }
            __syncthreads();
        }
#pragma unroll
        for (int mf = 0; mf < 4; ++mf) {
            int o = oc * 256 + wm * 64 + mf * 16 + (lane >> 2);
#pragma unroll
            for (int nf = 0; nf < 4; ++nf) {
                int nl = wn * 32 + nf * 8 + (lane & 3) * 2;
                int n = n0 + nl;
                if (n < Nn) {
                    float mk0 = s_any[nl] ? 1.f : 0.f;
                    float mk1 = s_any[nl + 1] ? 1.f : 0.f;
                    if (o < Oo) {
                        float bs = b2[o];
                        *(uint32_t*)(yp + (size_t)o * Nn + n) =
                            h2u(__floats2half2_rn((d[mf][nf][0] + bs) * mk0,
                                                  (d[mf][nf][1] + bs) * mk1));
                    }
                    if (o + 8 < Oo) {
                        float bs = b2[o + 8];
                        *(uint32_t*)(yp + (size_t)(o + 8) * Nn + n) =
                            h2u(__floats2half2_rn((d[mf][nf][2] + bs) * mk0,
                                                  (d[mf][nf][3] + bs) * mk1));
                    }
                }
            }
        }
        __syncthreads();
    }
}

template <int WSEL>
__global__ void wconv_kernel(const float* __restrict__ W, int rows, int cols, int orows) {
    __half* outp = (WSEL == 0) ? g_W0h : (WSEL == 1) ? g_W1h : g_W2h;
    int i = blockIdx.x * 256 + threadIdx.x;
    if (i >= orows * cols) return;
    int r = i / cols, c = i - r * cols;
    outp[(size_t)r * cols + c] = __float2half_rn((r < rows) ? W[(size_t)r * cols + c] : 0.f);
}

__global__ void coef_kernel() {
    int b = threadIdx.x;
    if (b >= Bb) return;
    float s = 0.f, d10 = 0.f, d25 = 0.f, d50 = 0.f;
    for (int j = 0; j < 100; ++j) {
        s += g_mask[b * Nn + j];
        if (j == 9)  d10 = s;
        if (j == 24) d25 = s;
        if (j == 49) d50 = s;
    }
    float d100 = s;
    for (int j = 0; j < 100; ++j) {
        float w = 0.25f / d100;
        if (j < 50) w += 0.25f / d50;
        if (j < 25) w += 0.25f / d25;
        if (j < 10) w += 0.25f / d10;
        g_coef[b * 128 + j] = g_mask[b * Nn + j] * w;
    }
}

// ---------------------------------------------------------------------------
// Top-100 over fp16 y: 12-bit first radix level (4096 packed u16 counters),
// parallel suffix-scan selection, 4-bit level 2. 512 threads (half the
// pass-iteration counts of the proven 256-thread version).
// ---------------------------------------------------------------------------
#define TKT 512
__global__ __launch_bounds__(TKT) void topk_kernel(float* __restrict__ out) {
    const int row = blockIdx.x, b = row / Oo, tid = threadIdx.x;
    __shared__ uint16_t su[Nn];          // 16000 B
    __shared__ uint32_t hist[2048];      // 4096 packed 16-bit counters (8KB)
    __shared__ uint32_t csum[256];
    __shared__ uint32_t s_sel[2];
    __shared__ uint32_t s_cnt;
    __shared__ uint32_t buf[128];
    __shared__ uint32_t srt[128];
    __shared__ float partial[TKT];

    for (int i = tid; i < 2048; i += TKT) hist[i] = 0;

    const uint32_t* yp = (const uint32_t*)(g_y + (size_t)row * Nn);
    for (int i = tid; i < Nn / 2; i += TKT) {
        uint32_t two = yp[i];
        uint32_t lo = two & 0xFFFFu, hi = two >> 16;
        su[2 * i]     = (uint16_t)((lo & 0x8000u) ? (~lo & 0xFFFFu) : (lo | 0x8000u));
        su[2 * i + 1] = (uint16_t)((hi & 0x8000u) ? (~hi & 0xFFFFu) : (hi | 0x8000u));
    }
    __syncthreads();

    // level 1: 12-bit histogram
    for (int i = tid; i < Nn; i += TKT) {
        uint32_t bin = (uint32_t)su[i] >> 4;
        atomicAdd(&hist[bin >> 1], 1u << ((bin & 1) * 16));
    }
    __syncthreads();

    // chunk sums (first 256 threads own 16 bins each)
    if (tid < 256) {
        uint32_t cs = 0;
#pragma unroll
        for (int w = 0; w < 8; ++w) {
            uint32_t v = hist[tid * 8 + w];
            cs += (v & 0xFFFFu) + (v >> 16);
        }
        csum[tid] = cs;
    }
    __syncthreads();
#pragma unroll
    for (int off = 1; off < 256; off <<= 1) {
        uint32_t v = (tid < 256 && tid + off < 256) ? csum[tid + off] : 0;
        __syncthreads();
        if (tid < 256) csum[tid] += v;
        __syncthreads();
    }
    int K = 100;
    if (tid < 256) {
        uint32_t sfx = csum[tid];
        uint32_t nxt = (tid < 255) ? csum[tid + 1] : 0;
        if (sfx >= (uint32_t)K && nxt < (uint32_t)K) {
            uint32_t above = nxt;
            int binSel = tid * 16;
            for (int bl = 15; bl >= 0; --bl) {
                int gb = tid * 16 + bl;
                uint32_t c = (hist[gb >> 1] >> ((gb & 1) * 16)) & 0xFFFFu;
                if (above + c >= (uint32_t)K) { binSel = gb; break; }
                above += c;
            }
            s_sel[0] = (uint32_t)binSel;
            s_sel[1] = (uint32_t)K - above;
        }
    }
    __syncthreads();
    const uint32_t bin12 = s_sel[0];
    K = (int)s_sel[1];
    __syncthreads();

    // level 2: 16 bins over low 4 bits
    if (tid < 16) csum[tid] = 0;
    __syncthreads();
    for (int i = tid; i < Nn; i += TKT) {
        uint32_t v = su[i];
        if ((v >> 4) == bin12) atomicAdd(&csum[v & 15u], 1u);
    }
    __syncthreads();
    if (tid == 0) {
        int cum = 0, bl = 15;
        for (; bl > 0; --bl) {
            int c = (int)csum[bl];
            if (cum + c >= K) break;
            cum += c;
        }
        s_sel[0] = (bin12 << 4) | (uint32_t)bl;
    }
    __syncthreads();
    const uint32_t thr = s_sel[0];

    if (tid == 0) s_cnt = 0;
    __syncthreads();
    for (int i = tid; i < Nn; i += TKT) {
        uint32_t v = su[i];
        if (v > thr) {
            uint32_t idx = atomicAdd(&s_cnt, 1u);
            if (idx < 128u) buf[idx] = v;
        }
    }
    __syncthreads();
    int g = (int)min(s_cnt, 100u);
    for (int j = g + tid; j < 100; j += TKT) buf[j] = thr;
    __syncthreads();

    if (tid < 100) {
        uint32_t v = buf[tid];
        int rank = 0;
#pragma unroll 4
        for (int j = 0; j < 100; ++j) {
            uint32_t w = buf[j];
            rank += (w > v) || (w == v && j < tid);
        }
        srt[rank] = v;
    }
    __syncthreads();
    float t = 0.f;
    if (tid < 100) {
        uint32_t u = srt[tid];
        uint16_t bits = (u & 0x8000u) ? (uint16_t)(u & 0x7FFFu) : (uint16_t)(~u & 0xFFFFu);
        t = __half2float(__ushort_as_half(bits)) * g_coef[b * 128 + tid];
    }
    partial[tid] = t;
    __syncthreads();
    for (int s = TKT / 2; s > 0; s >>= 1) {
        if (tid < s) partial[tid] += partial[tid + s];
        __syncthreads();
    }
    if (tid == 0) out[row] = partial[0];
}

extern "C" void kernel_launch(void* const* d_in, const int* in_sizes, int n_in,
                              void* d_out, int out_size) {
    const float* x  = (const float*)d_in[0];
    const float* W0 = (const float*)d_in[1];
    const float* b0 = (const float*)d_in[2];
    const float* W1 = (const float*)d_in[3];
    const float* b1 = (const float*)d_in[4];
    const float* W2 = (const float*)d_in[5];
    const float* b2 = (const float*)d_in[6];
    float* out = (float*)d_out;
    (void)in_sizes; (void)n_in; (void)out_size;

    cudaFuncSetAttribute(fused_mlp, cudaFuncAttributeMaxDynamicSharedMemorySize, DYN_SMEM);

    wconv_kernel<0><<<(Hh * Cc + 255) / 256, 256>>>(W0, Hh, Cc, Hh);
    wconv_kernel<1><<<(Hh * Hh + 255) / 256, 256>>>(W1, Hh, Hh, Hh);
    wconv_kernel<2><<<(Op * Hh + 255) / 256, 256>>>(W2, Oo, Hh, Op);

    fused_mlp<<<dim3(NTILE, 1, Bb), 512, DYN_SMEM>>>(x, b0, b1, b2);

    coef_kernel<<<1, 32>>>();
    topk_kernel<<<Bb * Oo, TKT>>>(out);
}

// round 16
// speedup vs baseline: 1.1111x; 1.0839x over previous
#include <cuda_runtime.h>
#include <cuda_fp16.h>
#include <stdint.h>

#define Bb 8
#define Cc 2048
#define Nn 8000
#define Hh 256
#define Oo 1000
#define Op 1024
#define NTILE 63
#define STAGE_A 20480            // 256 rows x 80B (32 f16 + 16B pad)
#define STAGE_B 8704             // 32 k-rows x 272B (128 f16 + 16B pad)
#define STAGE_BYTES (STAGE_A + STAGE_B)
#define NSTAGE 3
#define SMEM_H0 (NSTAGE * STAGE_BYTES)            // 87552
#define SMEM_H1 (SMEM_H0 + 256 * 272)             // 157184
#define DYN_SMEM (SMEM_H1 + 256 * 272)            // 226816

__device__ __align__(16) __half g_W0h[Hh * Cc];
__device__ __align__(16) __half g_W1h[Hh * Hh];
__device__ __align__(16) __half g_W2h[Op * Hh];
__device__ __align__(16) __half g_y [(size_t)Bb * Oo * Nn];   // fp16 y
__device__ float g_mask[Bb * Nn];
__device__ float g_coef[Bb * 128];

__device__ __forceinline__ uint32_t smem_u32(const void* p) {
    uint32_t a;
    asm("{ .reg .u64 t; cvta.to.shared.u64 t, %1; cvt.u32.u64 %0, t; }" : "=r"(a) : "l"(p));
    return a;
}
__device__ __forceinline__ void cp16(uint32_t dst, const void* src, int bytes) {
    asm volatile("cp.async.cg.shared.global [%0], [%1], 16, %2;\n"
                 :: "r"(dst), "l"(src), "r"(bytes) : "memory");
}
#define CP_COMMIT() asm volatile("cp.async.commit_group;\n" ::: "memory")
#define CP_WAIT0()  asm volatile("cp.async.wait_group 0;\n" ::: "memory")
#define CP_WAIT1()  asm volatile("cp.async.wait_group 1;\n" ::: "memory")

__device__ __forceinline__ void ldm_x4(uint32_t* r, const void* p) {
    uint32_t a = (uint32_t)__cvta_generic_to_shared(p);
    asm volatile("ldmatrix.sync.aligned.m8n8.x4.shared.b16 {%0,%1,%2,%3}, [%4];\n"
                 : "=r"(r[0]), "=r"(r[1]), "=r"(r[2]), "=r"(r[3]) : "r"(a));
}
__device__ __forceinline__ void ldm_x4t(uint32_t* r, const void* p) {
    uint32_t a = (uint32_t)__cvta_generic_to_shared(p);
    asm volatile("ldmatrix.sync.aligned.m8n8.x4.trans.shared.b16 {%0,%1,%2,%3}, [%4];\n"
                 : "=r"(r[0]), "=r"(r[1]), "=r"(r[2]), "=r"(r[3]) : "r"(a));
}
__device__ __forceinline__ void mma16816(float* d, const uint32_t* a, uint32_t b0, uint32_t b1) {
    asm volatile("mma.sync.aligned.m16n8k16.row.col.f32.f16.f16.f32 "
                 "{%0,%1,%2,%3}, {%4,%5,%6,%7}, {%8,%9}, {%0,%1,%2,%3};\n"
                 : "+f"(d[0]), "+f"(d[1]), "+f"(d[2]), "+f"(d[3])
                 : "r"(a[0]), "r"(a[1]), "r"(a[2]), "r"(a[3]), "r"(b0), "r"(b1));
}
__device__ __forceinline__ uint32_t h2u(__half2 h) { return *reinterpret_cast<uint32_t*>(&h); }

__device__ __forceinline__ void compute_iter(char* aB, char* bB, float d[4][4][4]) {
#pragma unroll
    for (int s = 0; s < 2; ++s) {
        uint32_t a[4][4];
#pragma unroll
        for (int mf = 0; mf < 4; ++mf) ldm_x4(a[mf], aB + mf * 16 * 80 + s * 32);
#pragma unroll
        for (int nf2 = 0; nf2 < 2; ++nf2) {
            uint32_t bq[4];
            ldm_x4t(bq, bB + s * 16 * 272 + nf2 * 32);
#pragma unroll
            for (int mf = 0; mf < 4; ++mf) {
                mma16816(d[mf][nf2 * 2],     a[mf], bq[0], bq[1]);
                mma16816(d[mf][nf2 * 2 + 1], a[mf], bq[2], bq[3]);
            }
        }
    }
}

// ---------------------------------------------------------------------------
// Fused 3-layer MLP per (b, n-tile of 128). h0/h1 stay in smem.
// (round-13 proven version — 474 us)
// ---------------------------------------------------------------------------
__global__ __launch_bounds__(512, 1) void fused_mlp(const float* __restrict__ x,
                                                    const float* __restrict__ b0,
                                                    const float* __restrict__ b1,
                                                    const float* __restrict__ b2) {
    extern __shared__ __align__(16) char dyn[];
    const uint32_t sm0 = smem_u32(dyn);
    __shared__ int s_any[128];

    const int tid = threadIdx.x, lane = tid & 31, warp = tid >> 5;
    const int wm = warp >> 2, wn = warp & 3;
    const int b = blockIdx.z, n0 = blockIdx.x * 128;

    const float* xb = x + (size_t)b * Cc * Nn;

    const int ar0 = tid >> 2, aseg = tid & 3;
    const int br = tid >> 4, bseg = tid & 15;
    const int bn = n0 + bseg * 8;

    char* const aLane = dyn + (wm * 64 + (lane & 15)) * 80 + ((lane >> 4) << 4);
    const int   bLane = (((lane >> 3) & 1) * 8 + (lane & 7)) * 272
                      + (wn * 32 + ((lane >> 4) << 3)) * 2;

    auto load_stageA = [&](int st, int kk, const __half* W, int Kd) {
        const uint32_t sa = sm0 + st * STAGE_BYTES;
        const int k0 = kk * 32;
        cp16(sa + ar0 * 80 + aseg * 16, W + (size_t)ar0 * Kd + k0 + aseg * 8, 16);
        cp16(sa + (ar0 + 128) * 80 + aseg * 16,
             W + (size_t)(ar0 + 128) * Kd + k0 + aseg * 8, 16);
    };

    float4 rb0, rb1;
    __half2 hm[4];
#pragma unroll
    for (int j = 0; j < 4; ++j) hm[j] = __floats2half2_rn(0.f, 0.f);
    if (tid < 128) s_any[tid] = 0;

    auto ldgB = [&](int kk, float4& a, float4& c) {
        if (bn < Nn) {
            const float* p = xb + (size_t)(kk * 32 + br) * Nn + bn;
            a = *(const float4*)p; c = *(const float4*)(p + 4);
        } else { a = make_float4(0.f, 0.f, 0.f, 0.f); c = a; }
    };
    auto stsB = [&](int st, const float4& a, const float4& c) {
        __half2 h0 = __floats2half2_rn(a.x, a.y), h1 = __floats2half2_rn(a.z, a.w);
        __half2 h2 = __floats2half2_rn(c.x, c.y), h3 = __floats2half2_rn(c.z, c.w);
        hm[0] = __hmax2(hm[0], h0); hm[1] = __hmax2(hm[1], h1);
        hm[2] = __hmax2(hm[2], h2); hm[3] = __hmax2(hm[3], h3);
        uint32_t dst = sm0 + st * STAGE_BYTES + STAGE_A + br * 272 + bseg * 16;
        asm volatile("st.shared.v4.b32 [%0], {%1,%2,%3,%4};\n"
                     :: "r"(dst), "r"(h2u(h0)), "r"(h2u(h1)), "r"(h2u(h2)), "r"(h2u(h3))
                     : "memory");
    };

    float d[4][4][4];
    auto zero_acc = [&]() {
#pragma unroll
        for (int i = 0; i < 4; ++i)
#pragma unroll
            for (int j = 0; j < 4; ++j) { d[i][j][0]=0.f; d[i][j][1]=0.f; d[i][j][2]=0.f; d[i][j][3]=0.f; }
    };
    auto epi_smem = [&](char* hs, const float* __restrict__ bias) {
#pragma unroll
        for (int mf = 0; mf < 4; ++mf) {
            int o = wm * 64 + mf * 16 + (lane >> 2);
            float bs0 = bias[o], bs1 = bias[o + 8];
#pragma unroll
            for (int nf = 0; nf < 4; ++nf) {
                int nl = wn * 32 + nf * 8 + (lane & 3) * 2;
                float v0 = fminf(fmaxf(d[mf][nf][0] + bs0, 0.f), 1e4f);
                float v1 = fminf(fmaxf(d[mf][nf][1] + bs0, 0.f), 1e4f);
                float v2 = fminf(fmaxf(d[mf][nf][2] + bs1, 0.f), 1e4f);
                float v3 = fminf(fmaxf(d[mf][nf][3] + bs1, 0.f), 1e4f);
                *(uint32_t*)(hs + o * 272 + nl * 2)       = h2u(__floats2half2_rn(v0, v1));
                *(uint32_t*)(hs + (o + 8) * 272 + nl * 2) = h2u(__floats2half2_rn(v2, v3));
            }
        }
    };

    // Phase 1: h0 = act(W0 @ x)
    zero_acc();
    {
        constexpr int NIT = Cc / 32;
        load_stageA(0, 0, g_W0h, Cc);
        { float4 a, c; ldgB(0, a, c); stsB(0, a, c); }
        CP_COMMIT();
        load_stageA(1, 1, g_W0h, Cc);
        ldgB(1, rb0, rb1);
        CP_COMMIT();
        CP_WAIT1();
        __syncthreads();
#pragma unroll 1
        for (int k = 0; k < NIT; ++k) {
            const int st = k % NSTAGE;
            if (k + 2 < NIT) { load_stageA((k + 2) % NSTAGE, k + 2, g_W0h, Cc); }
            if (k + 1 < NIT) stsB((k + 1) % NSTAGE, rb0, rb1);
            if (k + 2 < NIT) { ldgB(k + 2, rb0, rb1); CP_COMMIT(); }
            compute_iter(aLane + st * STAGE_BYTES,
                         dyn + st * STAGE_BYTES + STAGE_A + bLane, d);
            if (k + 2 < NIT)      { CP_WAIT1(); }
            else if (k + 1 < NIT) { CP_WAIT0(); }
            __syncthreads();
        }
    }
    epi_smem(dyn + SMEM_H0, b0);
#pragma unroll
    for (int j = 0; j < 4; ++j) {
        if (__low2float(hm[j])  > 0.f) atomicOr(&s_any[bseg * 8 + 2 * j],     1);
        if (__high2float(hm[j]) > 0.f) atomicOr(&s_any[bseg * 8 + 2 * j + 1], 1);
    }
    __syncthreads();
    if (tid < 128 && n0 + tid < Nn)
        g_mask[b * Nn + n0 + tid] = s_any[tid] ? 1.f : 0.f;

    // Phase 2: h1 = act(W1 @ h0)
    zero_acc();
    {
        constexpr int NIT = Hh / 32;
        load_stageA(0, 0, g_W1h, Hh); CP_COMMIT();
        load_stageA(1, 1, g_W1h, Hh); CP_COMMIT();
        CP_WAIT1();
        __syncthreads();
#pragma unroll 1
        for (int k = 0; k < NIT; ++k) {
            const int st = k % NSTAGE;
            if (k + 2 < NIT) { load_stageA((k + 2) % NSTAGE, k + 2, g_W1h, Hh); CP_COMMIT(); }
            compute_iter(aLane + st * STAGE_BYTES,
                         dyn + SMEM_H0 + k * (32 * 272) + bLane, d);
            if (k + 2 < NIT)      { CP_WAIT1(); }
            else if (k + 1 < NIT) { CP_WAIT0(); }
            __syncthreads();
        }
    }
    epi_smem(dyn + SMEM_H1, b1);
    __syncthreads();

    // Phase 3: y = (W2 @ h1 + b2) * mask  -> fp16
    __half* yp = g_y + (size_t)b * Oo * Nn;
#pragma unroll 1
    for (int oc = 0; oc < 4; ++oc) {
        const __half* W2c = g_W2h + (size_t)oc * 256 * Hh;
        zero_acc();
        constexpr int NIT = Hh / 32;
        load_stageA(0, 0, W2c, Hh); CP_COMMIT();
        load_stageA(1, 1, W2c, Hh); CP_COMMIT();
        CP_WAIT1();
        __syncthreads();
#pragma unroll 1
        for (int k = 0; k < NIT; ++k) {
            const int st = k % NSTAGE;
            if (k + 2 < NIT) { load_stageA((k + 2) % NSTAGE, k + 2, W2c, Hh); CP_COMMIT(); }
            compute_iter(aLane + st * STAGE_BYTES,
                         dyn + SMEM_H1 + k * (32 * 272) + bLane, d);
            if (k + 2 < NIT)      { CP_WAIT1(); }
            else if (k + 1 < NIT) { CP_WAIT0(); }
            __syncthreads();
        }
#pragma unroll
        for (int mf = 0; mf < 4; ++mf) {
            int o = oc * 256 + wm * 64 + mf * 16 + (lane >> 2);
#pragma unroll
            for (int nf = 0; nf < 4; ++nf) {
                int nl = wn * 32 + nf * 8 + (lane & 3) * 2;
                int n = n0 + nl;
                if (n < Nn) {
                    float mk0 = s_any[nl] ? 1.f : 0.f;
                    float mk1 = s_any[nl + 1] ? 1.f : 0.f;
                    if (o < Oo) {
                        float bs = b2[o];
                        *(uint32_t*)(yp + (size_t)o * Nn + n) =
                            h2u(__floats2half2_rn((d[mf][nf][0] + bs) * mk0,
                                                  (d[mf][nf][1] + bs) * mk1));
                    }
                    if (o + 8 < Oo) {
                        float bs = b2[o + 8];
                        *(uint32_t*)(yp + (size_t)(o + 8) * Nn + n) =
                            h2u(__floats2half2_rn((d[mf][nf][2] + bs) * mk0,
                                                  (d[mf][nf][3] + bs) * mk1));
                    }
                }
            }
        }
        __syncthreads();
    }
}

template <int WSEL>
__global__ void wconv_kernel(const float* __restrict__ W, int rows, int cols, int orows) {
    __half* outp = (WSEL == 0) ? g_W0h : (WSEL == 1) ? g_W1h : g_W2h;
    int i = blockIdx.x * 256 + threadIdx.x;
    if (i >= orows * cols) return;
    int r = i / cols, c = i - r * cols;
    outp[(size_t)r * cols + c] = __float2half_rn((r < rows) ? W[(size_t)r * cols + c] : 0.f);
}

__global__ void coef_kernel() {
    int b = threadIdx.x;
    if (b >= Bb) return;
    float s = 0.f, d10 = 0.f, d25 = 0.f, d50 = 0.f;
    for (int j = 0; j < 100; ++j) {
        s += g_mask[b * Nn + j];
        if (j == 9)  d10 = s;
        if (j == 24) d25 = s;
        if (j == 49) d50 = s;
    }
    float d100 = s;
    for (int j = 0; j < 100; ++j) {
        float w = 0.25f / d100;
        if (j < 50) w += 0.25f / d50;
        if (j < 25) w += 0.25f / d25;
        if (j < 10) w += 0.25f / d10;
        g_coef[b * 128 + j] = g_mask[b * Nn + j] * w;
    }
}

// ---------------------------------------------------------------------------
// Top-100 over fp16 y: keys held in REGISTERS (16 u32 = 32 keys/thread).
// 12-bit first radix level (4096 packed u16 counters), suffix-scan selection,
// 4-bit level 2. 192 pad keys (ordered 0, below any real key) counted then
// subtracted exactly.  256 threads.
// ---------------------------------------------------------------------------
#define NW 16   // u32 words per thread (256*16 = 4096 >= 4000)
__global__ __launch_bounds__(256) void topk_kernel(float* __restrict__ out) {
    const int row = blockIdx.x, b = row / Oo, tid = threadIdx.x;
    __shared__ uint32_t hist[2048];      // 4096 packed 16-bit counters (8KB)
    __shared__ uint32_t csum[256];
    __shared__ uint32_t s_sel[2];
    __shared__ uint32_t s_cnt;
    __shared__ uint32_t buf[128];
    __shared__ uint32_t srt[128];
    __shared__ float partial[256];

    for (int i = tid; i < 2048; i += 256) hist[i] = 0;

    // load all keys into registers (coalesced), convert to ordered u16 pairs
    const uint32_t* yp = (const uint32_t*)(g_y + (size_t)row * Nn);
    uint32_t kreg[NW];
#pragma unroll
    for (int w = 0; w < NW; ++w) {
        int idx = w * 256 + tid;
        uint32_t two = (idx < Nn / 2) ? yp[idx] : 0u;
        uint32_t lo = two & 0xFFFFu, hi = two >> 16;
        lo = (lo & 0x8000u) ? (~lo & 0xFFFFu) : (lo | 0x8000u);
        hi = (hi & 0x8000u) ? (~hi & 0xFFFFu) : (hi | 0x8000u);
        kreg[w] = (idx < Nn / 2) ? (lo | (hi << 16)) : 0u;   // pad = ordered key 0
    }
    __syncthreads();

    // level 1: 12-bit histogram from registers
#pragma unroll
    for (int w = 0; w < NW; ++w) {
        uint32_t v = kreg[w];
        uint32_t b0 = (v & 0xFFFFu) >> 4;
        uint32_t b1 = v >> 20;
        atomicAdd(&hist[b0 >> 1], 1u << ((b0 & 1) * 16));
        atomicAdd(&hist[b1 >> 1], 1u << ((b1 & 1) * 16));
    }
    __syncthreads();
    if (tid == 0) hist[0] -= 192u;   // remove pad keys (bin 0 low half)
    __syncthreads();

    // chunk sums: thread t owns bins [16t, 16t+16) = words [8t, 8t+8)
    {
        uint32_t cs = 0;
#pragma unroll
        for (int w = 0; w < 8; ++w) {
            uint32_t v = hist[tid * 8 + w];
            cs += (v & 0xFFFFu) + (v >> 16);
        }
        csum[tid] = cs;
    }
    __syncthreads();
#pragma unroll
    for (int off = 1; off < 256; off <<= 1) {
        uint32_t v = (tid + off < 256) ? csum[tid + off] : 0;
        __syncthreads();
        csum[tid] += v;
        __syncthreads();
    }
    int K = 100;
    {
        uint32_t sfx = csum[tid];
        uint32_t nxt = (tid < 255) ? csum[tid + 1] : 0;
        if (sfx >= (uint32_t)K && nxt < (uint32_t)K) {
            uint32_t above = nxt;
            int binSel = tid * 16;
            for (int bl = 15; bl >= 0; --bl) {
                int gb = tid * 16 + bl;
                uint32_t c = (hist[gb >> 1] >> ((gb & 1) * 16)) & 0xFFFFu;
                if (above + c >= (uint32_t)K) { binSel = gb; break; }
                above += c;
            }
            s_sel[0] = (uint32_t)binSel;
            s_sel[1] = (uint32_t)K - above;
        }
    }
    __syncthreads();
    const uint32_t bin12 = s_sel[0];
    K = (int)s_sel[1];
    __syncthreads();

    // level 2: 16 bins over low 4 bits, from registers
    if (tid < 16) csum[tid] = 0;
    __syncthreads();
#pragma unroll
    for (int w = 0; w < NW; ++w) {
        uint32_t v = kreg[w];
        uint32_t lo = v & 0xFFFFu, hi = v >> 16;
        if ((lo >> 4) == bin12) atomicAdd(&csum[lo & 15u], 1u);
        if ((hi >> 4) == bin12) atomicAdd(&csum[hi & 15u], 1u);
    }
    __syncthreads();
    if (tid == 0) {
        if (bin12 == 0) csum[0] -= 192u;   // pads land in (bin12=0, low4=0)
        int cum = 0, bl = 15;
        for (; bl > 0; --bl) {
            int c = (int)csum[bl];
            if (cum + c >= K) break;
            cum += c;
        }
        s_sel[0] = (bin12 << 4) | (uint32_t)bl;
    }
    __syncthreads();
    const uint32_t thr = s_sel[0];   // exact 16-bit key of the 100th-largest (>=1 > pad 0)

    if (tid == 0) s_cnt = 0;
    __syncthreads();
#pragma unroll
    for (int w = 0; w < NW; ++w) {
        uint32_t v = kreg[w];
        uint32_t lo = v & 0xFFFFu, hi = v >> 16;
        if (lo > thr) {
            uint32_t idx = atomicAdd(&s_cnt, 1u);
            if (idx < 128u) buf[idx] = lo;
        }
        if (hi > thr) {
            uint32_t idx = atomicAdd(&s_cnt, 1u);
            if (idx < 128u) buf[idx] = hi;
        }
    }
    __syncthreads();
    int g = (int)min(s_cnt, 100u);
    for (int j = g + tid; j < 100; j += 256) buf[j] = thr;   // fill ties
    __syncthreads();

    if (tid < 100) {
        uint32_t v = buf[tid];
        int rank = 0;
#pragma unroll 4
        for (int j = 0; j < 100; ++j) {
            uint32_t w = buf[j];
            rank += (w > v) || (w == v && j < tid);
        }
        srt[rank] = v;
    }
    __syncthreads();
    float t = 0.f;
    if (tid < 100) {
        uint32_t u = srt[tid];
        uint16_t bits = (u & 0x8000u) ? (uint16_t)(u & 0x7FFFu) : (uint16_t)(~u & 0xFFFFu);
        t = __half2float(__ushort_as_half(bits)) * g_coef[b * 128 + tid];
    }
    partial[tid] = t;
    __syncthreads();
    for (int s = 128; s > 0; s >>= 1) {
        if (tid < s) partial[tid] += partial[tid + s];
        __syncthreads();
    }
    if (tid == 0) out[row] = partial[0];
}

extern "C" void kernel_launch(void* const* d_in, const int* in_sizes, int n_in,
                              void* d_out, int out_size) {
    const float* x  = (const float*)d_in[0];
    const float* W0 = (const float*)d_in[1];
    const float* b0 = (const float*)d_in[2];
    const float* W1 = (const float*)d_in[3];
    const float* b1 = (const float*)d_in[4];
    const float* W2 = (const float*)d_in[5];
    const float* b2 = (const float*)d_in[6];
    float* out = (float*)d_out;
    (void)in_sizes; (void)n_in; (void)out_size;

    cudaFuncSetAttribute(fused_mlp, cudaFuncAttributeMaxDynamicSharedMemorySize, DYN_SMEM);

    wconv_kernel<0><<<(Hh * Cc + 255) / 256, 256>>>(W0, Hh, Cc, Hh);
    wconv_kernel<1><<<(Hh * Hh + 255) / 256, 256>>>(W1, Hh, Hh, Hh);
    wconv_kernel<2><<<(Op * Hh + 255) / 256, 256>>>(W2, Oo, Hh, Op);

    fused_mlp<<<dim3(NTILE, 1, Bb), 512, DYN_SMEM>>>(x, b0, b1, b2);

    coef_kernel<<<1, 32>>>();
    topk_kernel<<<Bb * Oo, 256>>>(out);
}

// round 17
// speedup vs baseline: 1.1133x; 1.0020x over previous
#include <cuda_runtime.h>
#include <cuda_fp16.h>
#include <stdint.h>

#define Bb 8
#define Cc 2048
#define Nn 8000
#define Hh 256
#define Oo 1000
#define Op 1024
#define NTILE 63
#define STAGE_A 20480            // 256 rows x 80B (32 f16 + 16B pad)
#define STAGE_B 8704             // 32 k-rows x 272B (128 f16 + 16B pad)
#define STAGE_BYTES (STAGE_A + STAGE_B)
#define NSTAGE 3
#define SMEM_H0 (NSTAGE * STAGE_BYTES)            // 87552
#define SMEM_H1 (SMEM_H0 + 256 * 272)             // 157184
#define DYN_SMEM (SMEM_H1 + 256 * 272)            // 226816

__device__ __align__(16) __half g_W0h[Hh * Cc];
__device__ __align__(16) __half g_W1h[Hh * Hh];
__device__ __align__(16) __half g_W2h[Op * Hh];
__device__ __align__(16) __half g_y [(size_t)Bb * Oo * Nn];   // fp16 y
__device__ float g_mask[Bb * Nn];
__device__ float g_coef[Bb * 128];

__device__ __forceinline__ uint32_t smem_u32(const void* p) {
    uint32_t a;
    asm("{ .reg .u64 t; cvta.to.shared.u64 t, %1; cvt.u32.u64 %0, t; }" : "=r"(a) : "l"(p));
    return a;
}
__device__ __forceinline__ void cp16(uint32_t dst, const void* src, int bytes) {
    asm volatile("cp.async.cg.shared.global [%0], [%1], 16, %2;\n"
                 :: "r"(dst), "l"(src), "r"(bytes) : "memory");
}
#define CP_COMMIT() asm volatile("cp.async.commit_group;\n" ::: "memory")
#define CP_WAIT0()  asm volatile("cp.async.wait_group 0;\n" ::: "memory")
#define CP_WAIT1()  asm volatile("cp.async.wait_group 1;\n" ::: "memory")

__device__ __forceinline__ void ldm_x4(uint32_t* r, const void* p) {
    uint32_t a = (uint32_t)__cvta_generic_to_shared(p);
    asm volatile("ldmatrix.sync.aligned.m8n8.x4.shared.b16 {%0,%1,%2,%3}, [%4];\n"
                 : "=r"(r[0]), "=r"(r[1]), "=r"(r[2]), "=r"(r[3]) : "r"(a));
}
__device__ __forceinline__ void ldm_x4t(uint32_t* r, const void* p) {
    uint32_t a = (uint32_t)__cvta_generic_to_shared(p);
    asm volatile("ldmatrix.sync.aligned.m8n8.x4.trans.shared.b16 {%0,%1,%2,%3}, [%4];\n"
                 : "=r"(r[0]), "=r"(r[1]), "=r"(r[2]), "=r"(r[3]) : "r"(a));
}
__device__ __forceinline__ void mma16816(float* d, const uint32_t* a, uint32_t b0, uint32_t b1) {
    asm volatile("mma.sync.aligned.m16n8k16.row.col.f32.f16.f16.f32 "
                 "{%0,%1,%2,%3}, {%4,%5,%6,%7}, {%8,%9}, {%0,%1,%2,%3};\n"
                 : "+f"(d[0]), "+f"(d[1]), "+f"(d[2]), "+f"(d[3])
                 : "r"(a[0]), "r"(a[1]), "r"(a[2]), "r"(a[3]), "r"(b0), "r"(b1));
}
__device__ __forceinline__ uint32_t h2u(__half2 h) { return *reinterpret_cast<uint32_t*>(&h); }

__device__ __forceinline__ void compute_iter(char* aB, char* bB, float d[4][4][4]) {
#pragma unroll
    for (int s = 0; s < 2; ++s) {
        uint32_t a[4][4];
#pragma unroll
        for (int mf = 0; mf < 4; ++mf) ldm_x4(a[mf], aB + mf * 16 * 80 + s * 32);
#pragma unroll
        for (int nf2 = 0; nf2 < 2; ++nf2) {
            uint32_t bq[4];
            ldm_x4t(bq, bB + s * 16 * 272 + nf2 * 32);
#pragma unroll
            for (int mf = 0; mf < 4; ++mf) {
                mma16816(d[mf][nf2 * 2],     a[mf], bq[0], bq[1]);
                mma16816(d[mf][nf2 * 2 + 1], a[mf], bq[2], bq[3]);
            }
        }
    }
}

// ---------------------------------------------------------------------------
// Fused 3-layer MLP per (b, n-tile of 128). h0/h1 stay in smem.
// (round-13 proven version — 474 us)
// ---------------------------------------------------------------------------
__global__ __launch_bounds__(512, 1) void fused_mlp(const float* __restrict__ x,
                                                    const float* __restrict__ b0,
                                                    const float* __restrict__ b1,
                                                    const float* __restrict__ b2) {
    extern __shared__ __align__(16) char dyn[];
    const uint32_t sm0 = smem_u32(dyn);
    __shared__ int s_any[128];

    const int tid = threadIdx.x, lane = tid & 31, warp = tid >> 5;
    const int wm = warp >> 2, wn = warp & 3;
    const int b = blockIdx.z, n0 = blockIdx.x * 128;

    const float* xb = x + (size_t)b * Cc * Nn;

    const int ar0 = tid >> 2, aseg = tid & 3;
    const int br = tid >> 4, bseg = tid & 15;
    const int bn = n0 + bseg * 8;

    char* const aLane = dyn + (wm * 64 + (lane & 15)) * 80 + ((lane >> 4) << 4);
    const int   bLane = (((lane >> 3) & 1) * 8 + (lane & 7)) * 272
                      + (wn * 32 + ((lane >> 4) << 3)) * 2;

    auto load_stageA = [&](int st, int kk, const __half* W, int Kd) {
        const uint32_t sa = sm0 + st * STAGE_BYTES;
        const int k0 = kk * 32;
        cp16(sa + ar0 * 80 + aseg * 16, W + (size_t)ar0 * Kd + k0 + aseg * 8, 16);
        cp16(sa + (ar0 + 128) * 80 + aseg * 16,
             W + (size_t)(ar0 + 128) * Kd + k0 + aseg * 8, 16);
    };

    float4 rb0, rb1;
    __half2 hm[4];
#pragma unroll
    for (int j = 0; j < 4; ++j) hm[j] = __floats2half2_rn(0.f, 0.f);
    if (tid < 128) s_any[tid] = 0;

    auto ldgB = [&](int kk, float4& a, float4& c) {
        if (bn < Nn) {
            const float* p = xb + (size_t)(kk * 32 + br) * Nn + bn;
            a = *(const float4*)p; c = *(const float4*)(p + 4);
        } else { a = make_float4(0.f, 0.f, 0.f, 0.f); c = a; }
    };
    auto stsB = [&](int st, const float4& a, const float4& c) {
        __half2 h0 = __floats2half2_rn(a.x, a.y), h1 = __floats2half2_rn(a.z, a.w);
        __half2 h2 = __floats2half2_rn(c.x, c.y), h3 = __floats2half2_rn(c.z, c.w);
        hm[0] = __hmax2(hm[0], h0); hm[1] = __hmax2(hm[1], h1);
        hm[2] = __hmax2(hm[2], h2); hm[3] = __hmax2(hm[3], h3);
        uint32_t dst = sm0 + st * STAGE_BYTES + STAGE_A + br * 272 + bseg * 16;
        asm volatile("st.shared.v4.b32 [%0], {%1,%2,%3,%4};\n"
                     :: "r"(dst), "r"(h2u(h0)), "r"(h2u(h1)), "r"(h2u(h2)), "r"(h2u(h3))
                     : "memory");
    };

    float d[4][4][4];
    auto zero_acc = [&]() {
#pragma unroll
        for (int i = 0; i < 4; ++i)
#pragma unroll
            for (int j = 0; j < 4; ++j) { d[i][j][0]=0.f; d[i][j][1]=0.f; d[i][j][2]=0.f; d[i][j][3]=0.f; }
    };
    auto epi_smem = [&](char* hs, const float* __restrict__ bias) {
#pragma unroll
        for (int mf = 0; mf < 4; ++mf) {
            int o = wm * 64 + mf * 16 + (lane >> 2);
            float bs0 = bias[o], bs1 = bias[o + 8];
#pragma unroll
            for (int nf = 0; nf < 4; ++nf) {
                int nl = wn * 32 + nf * 8 + (lane & 3) * 2;
                float v0 = fminf(fmaxf(d[mf][nf][0] + bs0, 0.f), 1e4f);
                float v1 = fminf(fmaxf(d[mf][nf][1] + bs0, 0.f), 1e4f);
                float v2 = fminf(fmaxf(d[mf][nf][2] + bs1, 0.f), 1e4f);
                float v3 = fminf(fmaxf(d[mf][nf][3] + bs1, 0.f), 1e4f);
                *(uint32_t*)(hs + o * 272 + nl * 2)       = h2u(__floats2half2_rn(v0, v1));
                *(uint32_t*)(hs + (o + 8) * 272 + nl * 2) = h2u(__floats2half2_rn(v2, v3));
            }
        }
    };

    // Phase 1: h0 = act(W0 @ x)
    zero_acc();
    {
        constexpr int NIT = Cc / 32;
        load_stageA(0, 0, g_W0h, Cc);
        { float4 a, c; ldgB(0, a, c); stsB(0, a, c); }
        CP_COMMIT();
        load_stageA(1, 1, g_W0h, Cc);
        ldgB(1, rb0, rb1);
        CP_COMMIT();
        CP_WAIT1();
        __syncthreads();
#pragma unroll 1
        for (int k = 0; k < NIT; ++k) {
            const int st = k % NSTAGE;
            if (k + 2 < NIT) { load_stageA((k + 2) % NSTAGE, k + 2, g_W0h, Cc); }
            if (k + 1 < NIT) stsB((k + 1) % NSTAGE, rb0, rb1);
            if (k + 2 < NIT) { ldgB(k + 2, rb0, rb1); CP_COMMIT(); }
            compute_iter(aLane + st * STAGE_BYTES,
                         dyn + st * STAGE_BYTES + STAGE_A + bLane, d);
            if (k + 2 < NIT)      { CP_WAIT1(); }
            else if (k + 1 < NIT) { CP_WAIT0(); }
            __syncthreads();
        }
    }
    epi_smem(dyn + SMEM_H0, b0);
#pragma unroll
    for (int j = 0; j < 4; ++j) {
        if (__low2float(hm[j])  > 0.f) atomicOr(&s_any[bseg * 8 + 2 * j],     1);
        if (__high2float(hm[j]) > 0.f) atomicOr(&s_any[bseg * 8 + 2 * j + 1], 1);
    }
    __syncthreads();
    if (tid < 128 && n0 + tid < Nn)
        g_mask[b * Nn + n0 + tid] = s_any[tid] ? 1.f : 0.f;

    // Phase 2: h1 = act(W1 @ h0)
    zero_acc();
    {
        constexpr int NIT = Hh / 32;
        load_stageA(0, 0, g_W1h, Hh); CP_COMMIT();
        load_stageA(1, 1, g_W1h, Hh); CP_COMMIT();
        CP_WAIT1();
        __syncthreads();
#pragma unroll 1
        for (int k = 0; k < NIT; ++k) {
            const int st = k % NSTAGE;
            if (k + 2 < NIT) { load_stageA((k + 2) % NSTAGE, k + 2, g_W1h, Hh); CP_COMMIT(); }
            compute_iter(aLane + st * STAGE_BYTES,
                         dyn + SMEM_H0 + k * (32 * 272) + bLane, d);
            if (k + 2 < NIT)      { CP_WAIT1(); }
            else if (k + 1 < NIT) { CP_WAIT0(); }
            __syncthreads();
        }
    }
    epi_smem(dyn + SMEM_H1, b1);
    __syncthreads();

    // Phase 3: y = (W2 @ h1 + b2) * mask  -> fp16
    __half* yp = g_y + (size_t)b * Oo * Nn;
#pragma unroll 1
    for (int oc = 0; oc < 4; ++oc) {
        const __half* W2c = g_W2h + (size_t)oc * 256 * Hh;
        zero_acc();
        constexpr int NIT = Hh / 32;
        load_stageA(0, 0, W2c, Hh); CP_COMMIT();
        load_stageA(1, 1, W2c, Hh); CP_COMMIT();
        CP_WAIT1();
        __syncthreads();
#pragma unroll 1
        for (int k = 0; k < NIT; ++k) {
            const int st = k % NSTAGE;
            if (k + 2 < NIT) { load_stageA((k + 2) % NSTAGE, k + 2, W2c, Hh); CP_COMMIT(); }
            compute_iter(aLane + st * STAGE_BYTES,
                         dyn + SMEM_H1 + k * (32 * 272) + bLane, d);
            if (k + 2 < NIT)      { CP_WAIT1(); }
            else if (k + 1 < NIT) { CP_WAIT0(); }
            __syncthreads();
        }
#pragma unroll
        for (int mf = 0; mf < 4; ++mf) {
            int o = oc * 256 + wm * 64 + mf * 16 + (lane >> 2);
#pragma unroll
            for (int nf = 0; nf < 4; ++nf) {
                int nl = wn * 32 + nf * 8 + (lane & 3) * 2;
                int n = n0 + nl;
                if (n < Nn) {
                    float mk0 = s_any[nl] ? 1.f : 0.f;
                    float mk1 = s_any[nl + 1] ? 1.f : 0.f;
                    if (o < Oo) {
                        float bs = b2[o];
                        *(uint32_t*)(yp + (size_t)o * Nn + n) =
                            h2u(__floats2half2_rn((d[mf][nf][0] + bs) * mk0,
                                                  (d[mf][nf][1] + bs) * mk1));
                    }
                    if (o + 8 < Oo) {
                        float bs = b2[o + 8];
                        *(uint32_t*)(yp + (size_t)(o + 8) * Nn + n) =
                            h2u(__floats2half2_rn((d[mf][nf][2] + bs) * mk0,
                                                  (d[mf][nf][3] + bs) * mk1));
                    }
                }
            }
        }
        __syncthreads();
    }
}

template <int WSEL>
__global__ void wconv_kernel(const float* __restrict__ W, int rows, int cols, int orows) {
    __half* outp = (WSEL == 0) ? g_W0h : (WSEL == 1) ? g_W1h : g_W2h;
    int i = blockIdx.x * 256 + threadIdx.x;
    if (i >= orows * cols) return;
    int r = i / cols, c = i - r * cols;
    outp[(size_t)r * cols + c] = __float2half_rn((r < rows) ? W[(size_t)r * cols + c] : 0.f);
}

__global__ void coef_kernel() {
    int b = threadIdx.x;
    if (b >= Bb) return;
    float s = 0.f, d10 = 0.f, d25 = 0.f, d50 = 0.f;
    for (int j = 0; j < 100; ++j) {
        s += g_mask[b * Nn + j];
        if (j == 9)  d10 = s;
        if (j == 24) d25 = s;
        if (j == 49) d50 = s;
    }
    float d100 = s;
    for (int j = 0; j < 100; ++j) {
        float w = 0.25f / d100;
        if (j < 50) w += 0.25f / d50;
        if (j < 25) w += 0.25f / d25;
        if (j < 10) w += 0.25f / d10;
        g_coef[b * 128 + j] = g_mask[b * Nn + j] * w;
    }
}

// ---------------------------------------------------------------------------
// Top-100 over fp16 y: register-resident keys (16 u32/thread), 12-bit first
// radix level, SHUFFLE-based suffix scan (2 barriers vs 17), 4-bit level 2.
// Pad correction folded into thread-0 chunk sum (only reader of hist[0];
// selected chunk is provably >= 4 since real keys >= 0x0400).
// ---------------------------------------------------------------------------
#define NW 16   // u32 words per thread (256*16 = 4096 >= 4000)
__global__ __launch_bounds__(256) void topk_kernel(float* __restrict__ out) {
    const int row = blockIdx.x, b = row / Oo, tid = threadIdx.x;
    const int lane = tid & 31, wid = tid >> 5;
    __shared__ uint32_t hist[2048];      // 4096 packed 16-bit counters (8KB)
    __shared__ uint32_t csum[256];
    __shared__ uint32_t ws[8];
    __shared__ uint32_t s_sel[2];
    __shared__ uint32_t s_cnt;
    __shared__ uint32_t buf[128];
    __shared__ uint32_t srt[128];
    __shared__ float partial[256];

    for (int i = tid; i < 2048; i += 256) hist[i] = 0;

    // load all keys into registers (coalesced), convert to ordered u16 pairs
    const uint32_t* yp = (const uint32_t*)(g_y + (size_t)row * Nn);
    uint32_t kreg[NW];
#pragma unroll
    for (int w = 0; w < NW; ++w) {
        int idx = w * 256 + tid;
        uint32_t two = (idx < Nn / 2) ? yp[idx] : 0u;
        uint32_t lo = two & 0xFFFFu, hi = two >> 16;
        lo = (lo & 0x8000u) ? (~lo & 0xFFFFu) : (lo | 0x8000u);
        hi = (hi & 0x8000u) ? (~hi & 0xFFFFu) : (hi | 0x8000u);
        kreg[w] = (idx < Nn / 2) ? (lo | (hi << 16)) : 0u;   // pad = ordered key 0
    }
    __syncthreads();

    // level 1: 12-bit histogram from registers
#pragma unroll
    for (int w = 0; w < NW; ++w) {
        uint32_t v = kreg[w];
        uint32_t b0 = (v & 0xFFFFu) >> 4;
        uint32_t b1 = v >> 20;
        atomicAdd(&hist[b0 >> 1], 1u << ((b0 & 1) * 16));
        atomicAdd(&hist[b1 >> 1], 1u << ((b1 & 1) * 16));
    }
    __syncthreads();

    // chunk sums (thread t owns bins [16t,16t+16)); thread 0 removes 192 pads
    uint32_t cs = 0;
    {
#pragma unroll
        for (int w = 0; w < 8; ++w) {
            uint32_t v = hist[tid * 8 + w];
            cs += (v & 0xFFFFu) + (v >> 16);
        }
        if (tid == 0) cs -= 192u;
    }
    // suffix scan: intra-warp shuffle + cross-warp combine (2 barriers)
    {
        uint32_t s = cs;
#pragma unroll
        for (int off = 1; off < 32; off <<= 1) {
            uint32_t v = __shfl_down_sync(0xFFFFFFFFu, s, off);
            if (lane + off < 32) s += v;
        }
        if (lane == 0) ws[wid] = s;   // warp total
        __syncthreads();
        uint32_t add = 0;
#pragma unroll
        for (int w2 = 0; w2 < 8; ++w2) if (w2 > wid) add += ws[w2];
        csum[tid] = s + add;
        __syncthreads();
    }
    int K = 100;
    {
        uint32_t sfx = csum[tid];
        uint32_t nxt = (tid < 255) ? csum[tid + 1] : 0;
        if (sfx >= (uint32_t)K && nxt < (uint32_t)K) {
            uint32_t above = nxt;
            int binSel = tid * 16;
            for (int bl = 15; bl >= 0; --bl) {
                int gb = tid * 16 + bl;
                uint32_t c = (hist[gb >> 1] >> ((gb & 1) * 16)) & 0xFFFFu;
                if (above + c >= (uint32_t)K) { binSel = gb; break; }
                above += c;
            }
            s_sel[0] = (uint32_t)binSel;
            s_sel[1] = (uint32_t)K - above;
        }
    }
    __syncthreads();
    const uint32_t bin12 = s_sel[0];
    K = (int)s_sel[1];
    __syncthreads();

    // level 2: 16 bins over low 4 bits, from registers
    if (tid < 16) csum[tid] = 0;
    __syncthreads();
#pragma unroll
    for (int w = 0; w < NW; ++w) {
        uint32_t v = kreg[w];
        uint32_t lo = v & 0xFFFFu, hi = v >> 16;
        if ((lo >> 4) == bin12) atomicAdd(&csum[lo & 15u], 1u);
        if ((hi >> 4) == bin12) atomicAdd(&csum[hi & 15u], 1u);
    }
    __syncthreads();
    if (tid == 0) {
        if (bin12 == 0) csum[0] -= 192u;   // unreachable in practice; kept for safety
        int cum = 0, bl = 15;
        for (; bl > 0; --bl) {
            int c = (int)csum[bl];
            if (cum + c >= K) break;
            cum += c;
        }
        s_sel[0] = (bin12 << 4) | (uint32_t)bl;
    }
    __syncthreads();
    const uint32_t thr = s_sel[0];   // exact 16-bit key of the 100th-largest

    if (tid == 0) s_cnt = 0;
    __syncthreads();
#pragma unroll
    for (int w = 0; w < NW; ++w) {
        uint32_t v = kreg[w];
        uint32_t lo = v & 0xFFFFu, hi = v >> 16;
        if (lo > thr) {
            uint32_t idx = atomicAdd(&s_cnt, 1u);
            if (idx < 128u) buf[idx] = lo;
        }
        if (hi > thr) {
            uint32_t idx = atomicAdd(&s_cnt, 1u);
            if (idx < 128u) buf[idx] = hi;
        }
    }
    __syncthreads();
    int g = (int)min(s_cnt, 100u);
    for (int j = g + tid; j < 100; j += 256) buf[j] = thr;   // fill ties
    __syncthreads();

    if (tid < 100) {
        uint32_t v = buf[tid];
        int rank = 0;
#pragma unroll 4
        for (int j = 0; j < 100; ++j) {
            uint32_t w = buf[j];
            rank += (w > v) || (w == v && j < tid);
        }
        srt[rank] = v;
    }
    __syncthreads();
    float t = 0.f;
    if (tid < 100) {
        uint32_t u = srt[tid];
        uint16_t bits = (u & 0x8000u) ? (uint16_t)(u & 0x7FFFu) : (uint16_t)(~u & 0xFFFFu);
        t = __half2float(__ushort_as_half(bits)) * g_coef[b * 128 + tid];
    }
    partial[tid] = t;
    __syncthreads();
    for (int s = 128; s > 0; s >>= 1) {
        if (tid < s) partial[tid] += partial[tid + s];
        __syncthreads();
    }
    if (tid == 0) out[row] = partial[0];
}

extern "C" void kernel_launch(void* const* d_in, const int* in_sizes, int n_in,
                              void* d_out, int out_size) {
    const float* x  = (const float*)d_in[0];
    const float* W0 = (const float*)d_in[1];
    const float* b0 = (const float*)d_in[2];
    const float* W1 = (const float*)d_in[3];
    const float* b1 = (const float*)d_in[4];
    const float* W2 = (const float*)d_in[5];
    const float* b2 = (const float*)d_in[6];
    float* out = (float*)d_out;
    (void)in_sizes; (void)n_in; (void)out_size;

    cudaFuncSetAttribute(fused_mlp, cudaFuncAttributeMaxDynamicSharedMemorySize, DYN_SMEM);

    wconv_kernel<0><<<(Hh * Cc + 255) / 256, 256>>>(W0, Hh, Cc, Hh);
    wconv_kernel<1><<<(Hh * Hh + 255) / 256, 256>>>(W1, Hh, Hh, Hh);
    wconv_kernel<2><<<(Op * Hh + 255) / 256, 256>>>(W2, Oo, Hh, Op);

    fused_mlp<<<dim3(NTILE, 1, Bb), 512, DYN_SMEM>>>(x, b0, b1, b2);

    coef_kernel<<<1, 32>>>();
    topk_kernel<<<Bb * Oo, 256>>>(out);
}